// round 4
// baseline (speedup 1.0000x reference)
#include <cuda_runtime.h>
#include <cuda_fp16.h>

// MeshGCN 2-layer GCN, N=100000, FEAT=16, E=3.2M.
// out_l[d] = dinv[d] * ( hs_l[d] + sum_{(s,d) in E} hs_l[s] ) + b_l
//   hs_l = (in_l @ W_l) * dinv,  dinv = rsqrt(deg_in + 1)
// CSR (dst-grouped) built per call; hs stored packed fp16 (32B/node) to halve
// random-gather sector traffic; accumulation in fp32; no atomics in the
// per-layer aggregation.

#define NMAX 100000
#define EMAX 3200000
#define F 16

__device__ int    g_deg[NMAX];
__device__ int    g_rowstart[NMAX + 1];
__device__ int    g_cursor[NMAX];
__device__ int    g_btot[512];
__device__ int    g_adj[EMAX];
__device__ float  g_dinv[NMAX];
__device__ __align__(16) uint4  g_hsh[NMAX * 2];   // fp16x2 packed: 32B per node
__device__ float4 g_agg[NMAX * 4];

__device__ __forceinline__ unsigned pack2(float a, float b) {
    __half2 h = __floats2half2_rn(a, b);
    return reinterpret_cast<unsigned&>(h);
}
__device__ __forceinline__ void acc8(uint4 v, float* a) {
    __half2 h; float2 f;
    h = reinterpret_cast<__half2&>(v.x); f = __half22float2(h); a[0] += f.x; a[1] += f.y;
    h = reinterpret_cast<__half2&>(v.y); f = __half22float2(h); a[2] += f.x; a[3] += f.y;
    h = reinterpret_cast<__half2&>(v.z); f = __half22float2(h); a[4] += f.x; a[5] += f.y;
    h = reinterpret_cast<__half2&>(v.w); f = __half22float2(h); a[6] += f.x; a[7] += f.y;
}

// ---------------- degree histogram ----------------
__global__ __launch_bounds__(256) void k_deg_init(int n) {
    int i = blockIdx.x * 256 + threadIdx.x;
    if (i < n) g_deg[i] = 0;
}

__global__ __launch_bounds__(256) void k_deg_accum(const int* __restrict__ dst, int E) {
    int e = blockIdx.x * 256 + threadIdx.x;
    if (e < E) atomicAdd(&g_deg[dst[e]], 1);   // no-return -> REDG
}

// ---------------- exclusive scan of g_deg -> g_rowstart ----------------
__global__ __launch_bounds__(256) void k_scan1(int n) {
    __shared__ int sh[256];
    int t = threadIdx.x;
    int i = blockIdx.x * 256 + t;
    int v = (i < n) ? g_deg[i] : 0;
    sh[t] = v;
    __syncthreads();
#pragma unroll
    for (int off = 1; off < 256; off <<= 1) {
        int a = (t >= off) ? sh[t - off] : 0;
        __syncthreads();
        sh[t] += a;
        __syncthreads();
    }
    if (i < n) g_rowstart[i] = sh[t] - v;
    if (t == 255) g_btot[blockIdx.x] = sh[255];
}

__global__ __launch_bounds__(512) void k_scan2(int nb) {
    __shared__ int sh[512];
    int t = threadIdx.x;
    int v = (t < nb) ? g_btot[t] : 0;
    sh[t] = v;
    __syncthreads();
#pragma unroll
    for (int off = 1; off < 512; off <<= 1) {
        int a = (t >= off) ? sh[t - off] : 0;
        __syncthreads();
        sh[t] += a;
        __syncthreads();
    }
    if (t < nb) g_btot[t] = sh[t] - v;
}

__global__ __launch_bounds__(256) void k_scan3(int n, int E) {
    int i = blockIdx.x * 256 + threadIdx.x;
    if (i < n) {
        int rs = g_rowstart[i] + g_btot[i >> 8];
        g_rowstart[i] = rs;
        g_cursor[i]   = rs;
    }
    if (i == n) g_rowstart[n] = E;
}

// ---------------- CSR fill (row order arbitrary; sum commutative) -------------
__global__ __launch_bounds__(256) void k_fill(const int* __restrict__ src,
                                              const int* __restrict__ dst, int E) {
    int e = blockIdx.x * 256 + threadIdx.x;
    if (e >= E) return;
    int d = dst[e];
    int pos = atomicAdd(&g_cursor[d], 1);
    g_adj[pos] = src[e];
}

// ---------------- dense: hs = (x @ W1) * dinv (fp16 packed) ----------------
__global__ __launch_bounds__(256) void k_pre1(const float* __restrict__ x,
                                              const float* __restrict__ W, int n) {
    __shared__ float sW[256];
    int tid = threadIdx.x;
    sW[tid] = W[tid];
    __syncthreads();
    int i = blockIdx.x * 256 + tid;
    if (i >= n) return;

    const float4* xp = reinterpret_cast<const float4*>(x) + (size_t)i * 4;
    float xr[16];
#pragma unroll
    for (int c = 0; c < 4; c++) {
        float4 t = xp[c];
        xr[c * 4 + 0] = t.x; xr[c * 4 + 1] = t.y;
        xr[c * 4 + 2] = t.z; xr[c * 4 + 3] = t.w;
    }
    float acc[16];
#pragma unroll
    for (int j = 0; j < 16; j++) acc[j] = 0.0f;
#pragma unroll
    for (int k = 0; k < 16; k++) {
        float xk = xr[k];
#pragma unroll
        for (int j = 0; j < 16; j++) acc[j] += xk * sW[k * 16 + j];
    }
    float dv = rsqrtf((float)(g_deg[i] + 1));
    g_dinv[i] = dv;
#pragma unroll
    for (int j = 0; j < 16; j++) acc[j] *= dv;
    uint4 u0 = make_uint4(pack2(acc[0], acc[1]),  pack2(acc[2], acc[3]),
                          pack2(acc[4], acc[5]),  pack2(acc[6], acc[7]));
    uint4 u1 = make_uint4(pack2(acc[8], acc[9]),  pack2(acc[10], acc[11]),
                          pack2(acc[12], acc[13]), pack2(acc[14], acc[15]));
    g_hsh[(size_t)i * 2 + 0] = u0;
    g_hsh[(size_t)i * 2 + 1] = u1;
}

// ---------------- CSR aggregation: warp/node, 2 lanes/edge, fp32 accum -------
// agg[node] = hs[node] + sum_{s in adj[row]} hs[s]
__global__ __launch_bounds__(256) void k_agg(int n) {
    int lane = threadIdx.x & 31;
    int node = blockIdx.x * 8 + (threadIdx.x >> 5);
    if (node >= n) return;
    int c = lane & 1;        // which 16B half of the 32B node record
    int g = lane >> 1;       // neighbor slot within chunk (0..15)

    int beg = g_rowstart[node];
    int end = g_rowstart[node + 1];

    float acc[8];
#pragma unroll
    for (int j = 0; j < 8; j++) acc[j] = 0.0f;
    if (g == 0) {            // self-loop seed
        uint4 v = g_hsh[(size_t)node * 2 + c];
        acc8(v, acc);
    }

    for (int base = beg; base < end; base += 32) {
        int sidx = (base + lane < end) ? __ldg(&g_adj[base + lane]) : 0;
        int nch = end - base; if (nch > 32) nch = 32;
        int iters = (nch + 15) >> 4;
#pragma unroll 2
        for (int it = 0; it < iters; it++) {
            int idx = it * 16 + g;
            int s = __shfl_sync(0xffffffffu, sidx, idx & 31);
            if (idx < nch) {
                uint4 v = __ldg(&g_hsh[(size_t)s * 2 + c]);
                acc8(v, acc);
            }
        }
    }
    // reduce across the 16 neighbor slots (lanes equal in c: bits 1..4)
#pragma unroll
    for (int off = 2; off <= 16; off <<= 1) {
#pragma unroll
        for (int j = 0; j < 8; j++)
            acc[j] += __shfl_xor_sync(0xffffffffu, acc[j], off);
    }
    if (g == 0) {
        g_agg[(size_t)node * 4 + c * 2 + 0] = make_float4(acc[0], acc[1], acc[2], acc[3]);
        g_agg[(size_t)node * 4 + c * 2 + 1] = make_float4(acc[4], acc[5], acc[6], acc[7]);
    }
}

// ---------------- y = relu(dinv*agg + b1) ; hs = (y @ W2) * dinv (fp16) ------
__global__ __launch_bounds__(256) void k_mid(const float* __restrict__ W2,
                                             const float* __restrict__ b1, int n) {
    __shared__ float sW[256];
    __shared__ float sb[16];
    int tid = threadIdx.x;
    sW[tid] = W2[tid];
    if (tid < 16) sb[tid] = b1[tid];
    __syncthreads();
    int i = blockIdx.x * 256 + tid;
    if (i >= n) return;

    float dv = g_dinv[i];
    float y[16];
#pragma unroll
    for (int c = 0; c < 4; c++) {
        float4 a = g_agg[(size_t)i * 4 + c];
        float v0 = a.x * dv + sb[c * 4 + 0];
        float v1 = a.y * dv + sb[c * 4 + 1];
        float v2 = a.z * dv + sb[c * 4 + 2];
        float v3 = a.w * dv + sb[c * 4 + 3];
        y[c * 4 + 0] = v0 > 0.0f ? v0 : 0.0f;
        y[c * 4 + 1] = v1 > 0.0f ? v1 : 0.0f;
        y[c * 4 + 2] = v2 > 0.0f ? v2 : 0.0f;
        y[c * 4 + 3] = v3 > 0.0f ? v3 : 0.0f;
    }
    float acc[16];
#pragma unroll
    for (int j = 0; j < 16; j++) acc[j] = 0.0f;
#pragma unroll
    for (int k = 0; k < 16; k++) {
        float yk = y[k];
#pragma unroll
        for (int j = 0; j < 16; j++) acc[j] += yk * sW[k * 16 + j];
    }
#pragma unroll
    for (int j = 0; j < 16; j++) acc[j] *= dv;
    uint4 u0 = make_uint4(pack2(acc[0], acc[1]),  pack2(acc[2], acc[3]),
                          pack2(acc[4], acc[5]),  pack2(acc[6], acc[7]));
    uint4 u1 = make_uint4(pack2(acc[8], acc[9]),  pack2(acc[10], acc[11]),
                          pack2(acc[12], acc[13]), pack2(acc[14], acc[15]));
    g_hsh[(size_t)i * 2 + 0] = u0;
    g_hsh[(size_t)i * 2 + 1] = u1;
}

// ---------------- out = dinv*agg + b2 ----------------
__global__ __launch_bounds__(256) void k_final(const float* __restrict__ b2,
                                               float* __restrict__ out, int n) {
    __shared__ float sb[16];
    int tid = threadIdx.x;
    if (tid < 16) sb[tid] = b2[tid];
    __syncthreads();
    int i = blockIdx.x * 256 + tid;
    if (i >= n) return;

    float dv = g_dinv[i];
    float4* op = reinterpret_cast<float4*>(out) + (size_t)i * 4;
#pragma unroll
    for (int c = 0; c < 4; c++) {
        float4 a = g_agg[(size_t)i * 4 + c];
        float4 o;
        o.x = a.x * dv + sb[c * 4 + 0];
        o.y = a.y * dv + sb[c * 4 + 1];
        o.z = a.z * dv + sb[c * 4 + 2];
        o.w = a.w * dv + sb[c * 4 + 3];
        op[c] = o;
    }
}

extern "C" void kernel_launch(void* const* d_in, const int* in_sizes, int n_in,
                              void* d_out, int out_size) {
    const float* x  = (const float*)d_in[0];
    const int*   ei = (const int*)  d_in[1];
    const float* W1 = (const float*)d_in[2];
    const float* b1 = (const float*)d_in[3];
    const float* W2 = (const float*)d_in[4];
    const float* b2 = (const float*)d_in[5];
    float* out = (float*)d_out;

    int E = in_sizes[1] / 2;
    int n = in_sizes[0] / F;
    const int* src = ei;
    const int* dst = ei + E;

    int nb_n  = (n + 255) / 256;
    int nb_n1 = (n + 256) / 256;
    int nb_e  = (E + 255) / 256;
    int nb_w  = (n + 7) / 8;

    k_deg_init <<<nb_n, 256>>>(n);
    k_deg_accum<<<nb_e, 256>>>(dst, E);
    k_scan1    <<<nb_n, 256>>>(n);
    k_scan2    <<<1,    512>>>(nb_n);
    k_scan3    <<<nb_n1,256>>>(n, E);
    k_fill     <<<nb_e, 256>>>(src, dst, E);
    k_pre1     <<<nb_n, 256>>>(x, W1, n);
    k_agg      <<<nb_w, 256>>>(n);
    k_mid      <<<nb_n, 256>>>(W2, b1, n);
    k_agg      <<<nb_w, 256>>>(n);
    k_final    <<<nb_n, 256>>>(b2, out, n);
}